// round 2
// baseline (speedup 1.0000x reference)
#include <cuda_runtime.h>
#include <cstdint>

#define RADIUS 5
#define RS 11           // region size
#define EMB 128
#define BB 32
#define LL 512
#define NPOS (BB * LL)  // 16384

__global__ __launch_bounds__(256) void region_encoder_kernel(
    const int* __restrict__ seq32,
    const float* __restrict__ W,
    const float* __restrict__ U,
    float* __restrict__ out)
{
    const int warp = blockIdx.x * 8 + (threadIdx.x >> 5);
    const int lane = threadIdx.x & 31;

    const int b = warp >> 9;          // / LL
    const int l = warp & (LL - 1);    // % LL

    // ---- dtype detection + window load, all in flight together ----
    // Lanes 16..31 sample odd 32-bit words of the first 128B of seq.
    // int64 (little-endian) layout => all odd words are zero.
    // int32 layout => tokens uniform in [0,50000), essentially never all zero.
    int det = 0;
    if (lane >= 16) det = seq32[((lane - 16) << 1) + 1];

    // Speculative int32-layout window token load (lanes 0..10).
    const int p = l - RADIUS + lane;
    const bool inwin = (lane < RS) && ((unsigned)p < (unsigned)LL);
    const int idx = b * LL + p;
    int tok = inwin ? __ldg(seq32 + idx) : 0;

    const unsigned ball = __ballot_sync(0xffffffffu, det != 0);
    if (ball == 0u) {
        // int64 layout: re-load low words at idx*2 (rare/cold path).
        tok = inwin ? __ldg(seq32 + (idx << 1)) : 0;
    }

    const int center = __shfl_sync(0xffffffffu, tok, RADIUS);

    // ---- front-batched gathers: 1 W row + 11 U rows, 12 independent LDG.128 ----
    const float4 w =
        __ldg(reinterpret_cast<const float4*>(W + (size_t)center * EMB) + lane);

    float4 u[RS];
#pragma unroll
    for (int j = 0; j < RS; j++) {
        const int tj = __shfl_sync(0xffffffffu, tok, j);
        const float4* row =
            reinterpret_cast<const float4*>(U + ((size_t)tj * RS + j) * EMB);
        u[j] = __ldcs(row + lane);   // streaming: keep W resident in L2
    }

    float4 acc;
    acc.x = u[0].x * w.x;
    acc.y = u[0].y * w.y;
    acc.z = u[0].z * w.z;
    acc.w = u[0].w * w.w;
#pragma unroll
    for (int j = 1; j < RS; j++) {
        acc.x = fmaxf(acc.x, u[j].x * w.x);
        acc.y = fmaxf(acc.y, u[j].y * w.y);
        acc.z = fmaxf(acc.z, u[j].z * w.z);
        acc.w = fmaxf(acc.w, u[j].w * w.w);
    }

    const float m = (center != 0) ? 1.0f : 0.0f;
    acc.x *= m; acc.y *= m; acc.z *= m; acc.w *= m;

    __stcs(reinterpret_cast<float4*>(out + (size_t)warp * EMB) + lane, acc);
}

extern "C" void kernel_launch(void* const* d_in, const int* in_sizes, int n_in,
                              void* d_out, int out_size) {
    const int*   seq32 = (const int*)d_in[0];
    const float* W     = (const float*)d_in[1];
    const float* U     = (const float*)d_in[2];
    float*       out   = (float*)d_out;

    const int threads = 256;                   // 8 warps/block
    const int blocks  = NPOS / (threads / 32); // 2048
    region_encoder_kernel<<<blocks, threads>>>(seq32, W, U, out);
}

// round 3
// speedup vs baseline: 1.2931x; 1.2931x over previous
#include <cuda_runtime.h>
#include <cstdint>

#define RADIUS 5
#define RS 11           // region size
#define EMB 128
#define BB 32
#define LL 512
#define NPOS (BB * LL)  // 16384

// minBlocksPerMultiprocessor=4 -> 1024 threads/SM -> 64-reg/thread budget:
// enough for ptxas to keep all 11 float4 U rows live and front-batch the loads.
__global__ __launch_bounds__(256, 4) void region_encoder_kernel(
    const int* __restrict__ seq32,
    const float* __restrict__ W,
    const float* __restrict__ U,
    float* __restrict__ out)
{
    const int warp = blockIdx.x * 8 + (threadIdx.x >> 5);
    const int lane = threadIdx.x & 31;

    const int b = warp >> 9;          // / LL
    const int l = warp & (LL - 1);    // % LL

    // ---- dtype detection + window load, all in flight together ----
    // Lanes 16..31 sample odd 32-bit words of the first 128B of seq.
    // int64 (little-endian) layout => all odd words zero; int32 layout =>
    // tokens uniform in [0,50000), essentially never all zero.
    int det = 0;
    if (lane >= 16) det = seq32[((lane - 16) << 1) + 1];

    // Speculative int32-layout window token load (lanes 0..10).
    const int p = l - RADIUS + lane;
    const bool inwin = (lane < RS) && ((unsigned)p < (unsigned)LL);
    const int idx = b * LL + p;
    int tok = inwin ? __ldg(seq32 + idx) : 0;

    const unsigned ball = __ballot_sync(0xffffffffu, det != 0);
    if (ball == 0u) {
        // int64 layout: re-load low words at idx*2 (cold path).
        tok = inwin ? __ldg(seq32 + (idx << 1)) : 0;
    }

    const int center = __shfl_sync(0xffffffffu, tok, RADIUS);

    // ---- front-batched gathers: 1 W row + 11 U rows = 12 independent LDG.128 ----
    const float4 w =
        __ldg(reinterpret_cast<const float4*>(W + (size_t)center * EMB) + lane);

    float4 u[RS];
#pragma unroll
    for (int j = 0; j < RS; j++) {
        const int tj = __shfl_sync(0xffffffffu, tok, j);
        const float4* row =
            reinterpret_cast<const float4*>(U + ((size_t)tj * RS + j) * EMB);
        u[j] = __ldg(row + lane);    // default caching: keep the ~13% U reuse in L2
    }

    float4 acc;
    acc.x = u[0].x * w.x;
    acc.y = u[0].y * w.y;
    acc.z = u[0].z * w.z;
    acc.w = u[0].w * w.w;
#pragma unroll
    for (int j = 1; j < RS; j++) {
        acc.x = fmaxf(acc.x, u[j].x * w.x);
        acc.y = fmaxf(acc.y, u[j].y * w.y);
        acc.z = fmaxf(acc.z, u[j].z * w.z);
        acc.w = fmaxf(acc.w, u[j].w * w.w);
    }

    const float m = (center != 0) ? 1.0f : 0.0f;
    acc.x *= m; acc.y *= m; acc.z *= m; acc.w *= m;

    // Output is write-once streaming: don't pollute L2 with it.
    __stcs(reinterpret_cast<float4*>(out + (size_t)warp * EMB) + lane, acc);
}

extern "C" void kernel_launch(void* const* d_in, const int* in_sizes, int n_in,
                              void* d_out, int out_size) {
    const int*   seq32 = (const int*)d_in[0];
    const float* W     = (const float*)d_in[1];
    const float* U     = (const float*)d_in[2];
    float*       out   = (float*)d_out;

    const int threads = 256;                   // 8 warps/block
    const int blocks  = NPOS / (threads / 32); // 2048
    region_encoder_kernel<<<blocks, threads>>>(seq32, W, U, out);
}